// round 1
// baseline (speedup 1.0000x reference)
#include <cuda_runtime.h>

// Problem constants (static per reference)
#define NEV   250000
#define CB    9
#define HV    180
#define WV    240
#define BB    8
#define PLANE (HV*WV)              // 43200
#define NVOX  (2*CB*PLANE*BB)      // 6,220,800
#define TABN  8193                 // table entries over s in [-1,1], h = 2/8192
#define OUTSZ 640

__device__ float        g_vox[NVOX];
__device__ float        g_tab[TABN];
__device__ unsigned int g_bmax[BB];

// ---------------------------------------------------------------------------
// 0) zero vox / table / bmax (d_out is poisoned, vox accumulates every call)
// ---------------------------------------------------------------------------
__global__ void k_init() {
    int i = blockIdx.x * blockDim.x + threadIdx.x;
    if (i < NVOX / 4) ((float4*)g_vox)[i] = make_float4(0.f, 0.f, 0.f, 0.f);
    if (i < TABN) g_tab[i] = 0.f;
    if (i < BB)   g_bmax[i] = 0u;
}

// ---------------------------------------------------------------------------
// 1) per-batch max of t (positive floats: uint bit-pattern order == float order)
// ---------------------------------------------------------------------------
__global__ void k_segmax(const float* __restrict__ ev) {
    __shared__ unsigned int sm[BB];
    if (threadIdx.x < BB) sm[threadIdx.x] = 0u;
    __syncthreads();
    for (int e = blockIdx.x * blockDim.x + threadIdx.x; e < NEV;
         e += gridDim.x * blockDim.x) {
        float t = ev[5 * e + 2];
        int   b = (int)ev[5 * e + 4];
        atomicMax(&sm[b], __float_as_uint(t));
    }
    __syncthreads();
    if (threadIdx.x < BB) atomicMax(&g_bmax[threadIdx.x], sm[threadIdx.x]);
}

// ---------------------------------------------------------------------------
// 2) tabulate f(s) = W3·lrelu(W2·lrelu(W1 s + b1) + b2) + b3 on uniform grid.
//    Split the 100 output neurons over gridDim.y (4 chunks of 25) for occupancy;
//    partial sums combined via atomicAdd on the zeroed table.
// ---------------------------------------------------------------------------
#define KCH 25
__global__ void k_table(const float* __restrict__ W1, const float* __restrict__ b1,
                        const float* __restrict__ W2, const float* __restrict__ b2,
                        const float* __restrict__ W3, const float* __restrict__ b3) {
    __shared__ float sW2[100 * KCH];
    __shared__ float sW1[100], sb1[100];
    int k0 = blockIdx.y * KCH;
    for (int i = threadIdx.x; i < 100 * KCH; i += blockDim.x)
        sW2[i] = W2[(i / KCH) * 100 + k0 + (i % KCH)];
    for (int i = threadIdx.x; i < 100; i += blockDim.x) {
        sW1[i] = W1[i];
        sb1[i] = b1[i];
    }
    __syncthreads();
    int e = blockIdx.x * blockDim.x + threadIdx.x;
    if (e >= TABN) return;
    float s = (float)e * (2.0f / 8192.0f) - 1.0f;
    float acc[KCH];
#pragma unroll
    for (int k = 0; k < KCH; k++) acc[k] = 0.f;
#pragma unroll 4
    for (int j = 0; j < 100; j++) {
        float pre = fmaf(sW1[j], s, sb1[j]);
        float hj  = fmaxf(pre, 0.1f * pre);   // LeakyReLU(0.1)
#pragma unroll
        for (int k = 0; k < KCH; k++)
            acc[k] = fmaf(hj, sW2[j * KCH + k], acc[k]);
    }
    float f = (blockIdx.y == 0) ? b3[0] : 0.f;
#pragma unroll
    for (int k = 0; k < KCH; k++) {
        float pre = acc[k] + b2[k0 + k];
        float h2  = fmaxf(pre, 0.1f * pre);
        f = fmaf(h2, W3[k0 + k], f);
    }
    atomicAdd(&g_tab[e], f);
}

// ---------------------------------------------------------------------------
// 3) scatter: 9 bins per event. Bin shift i/8 == exactly 512 table cells, so
//    one float->grid conversion serves all 9 lookups. clip() in the reference
//    is a no-op (indices provably in range).
// ---------------------------------------------------------------------------
__global__ void k_scatter(const float* __restrict__ ev) {
    int e = blockIdx.x * blockDim.x + threadIdx.x;
    if (e >= NEV) return;
    float x = ev[5 * e + 0], y = ev[5 * e + 1], t = ev[5 * e + 2];
    float p = ev[5 * e + 3], bf = ev[5 * e + 4];
    int b = (int)bf;
    float tn = t / __uint_as_float(g_bmax[b]);      // matches jnp fp32 divide
    int base = (int)x + WV * (int)y + (CB * PLANE) * (int)p + (2 * CB * PLANE) * b;
    float u0 = (tn + 1.0f) * 4096.0f;               // grid coord of s = tn - 0
#pragma unroll
    for (int i = 0; i < CB; i++) {
        float u = u0 - 512.0f * (float)i;           // exact fp32 arithmetic
        int i0 = (int)u;
        if (i0 > TABN - 2) i0 = TABN - 2;           // tn == 1.0 edge
        float fr = u - (float)i0;
        float t0 = g_tab[i0], t1 = g_tab[i0 + 1];
        float val = tn * fmaf(fr, t1 - t0, t0);
        atomicAdd(&g_vox[base + i * PLANE], val);
    }
}

// ---------------------------------------------------------------------------
// 4) letterbox bilinear resize (180,240)->(480,640), pad rows with 114.
//    scale = 8/3 exactly: per 8 output columns the bilinear weights are
//    compile-time constants and inputs span 5 columns. fx/fy are exact dyadic
//    fp32 values identical to jax's (o+0.5)*0.375-0.5; index clamping at the
//    borders reproduces jax's weight renormalization for the linear kernel.
//    One thread: 8 pixels, 10 loads, 2 x STG.128.
// ---------------------------------------------------------------------------
__global__ void k_resize(float* __restrict__ out) {
    int gid = blockIdx.x * blockDim.x + threadIdx.x;   // 8*18*640*80 = 7,372,800
    if (gid >= BB * 2 * CB * OUTSZ * (OUTSZ / 8)) return;
    int m  = gid % (OUTSZ / 8);
    int r  = gid / (OUTSZ / 8);
    int oy = r % OUTSZ;
    int bc = r / OUTSZ;                                // b*18 + c
    float* o = out + (((size_t)bc * OUTSZ + oy) * OUTSZ + m * 8);
    if (oy < 80 || oy >= 560) {
        float4 v = make_float4(114.f, 114.f, 114.f, 114.f);
        ((float4*)o)[0] = v;
        ((float4*)o)[1] = v;
        return;
    }
    int c = bc % (2 * CB), b = bc / (2 * CB);
    int pp = c / CB, bin = c % CB;
    const float* vb = g_vox + (size_t)PLANE * (bin + CB * (pp + 2 * b));

    int oyr = oy - 80;
    float fy  = 0.375f * (float)oyr - 0.3125f;
    float fyf = floorf(fy);
    int   y0  = (int)fyf;
    float wy  = fy - fyf;
    int y0c = y0 < 0 ? 0 : y0;
    int y1c = (y0 + 1 > HV - 1) ? (HV - 1) : (y0 + 1);
    const float* r0 = vb + y0c * WV;
    const float* r1 = vb + y1c * WV;

    int xb = 3 * m - 1;
    float a0[5], a1[5];
#pragma unroll
    for (int i = 0; i < 5; i++) {
        int xc = xb + i;
        xc = xc < 0 ? 0 : (xc > WV - 1 ? WV - 1 : xc);
        a0[i] = r0[xc];
        a1[i] = r1[xc];
    }
    const float wx[8] = {0.6875f, 0.0625f, 0.4375f, 0.8125f,
                         0.1875f, 0.5625f, 0.9375f, 0.3125f};
    const int   ix[8] = {0, 1, 1, 1, 2, 2, 2, 3};
    float o8[8];
#pragma unroll
    for (int k = 0; k < 8; k++) {
        int i = ix[k];
        float h0 = fmaf(wx[k], a0[i + 1] - a0[i], a0[i]);
        float h1 = fmaf(wx[k], a1[i + 1] - a1[i], a1[i]);
        o8[k] = fmaf(wy, h1 - h0, h0);
    }
    ((float4*)o)[0] = make_float4(o8[0], o8[1], o8[2], o8[3]);
    ((float4*)o)[1] = make_float4(o8[4], o8[5], o8[6], o8[7]);
}

// ---------------------------------------------------------------------------
// launch: inputs per metadata order:
// events, W1, b1, W2, b2, W3, b3, batch_size(unused; B=8 static)
// ---------------------------------------------------------------------------
extern "C" void kernel_launch(void* const* d_in, const int* in_sizes, int n_in,
                              void* d_out, int out_size) {
    const float* ev = (const float*)d_in[0];
    const float* W1 = (const float*)d_in[1];
    const float* b1 = (const float*)d_in[2];
    const float* W2 = (const float*)d_in[3];
    const float* b2 = (const float*)d_in[4];
    const float* W3 = (const float*)d_in[5];
    const float* b3 = (const float*)d_in[6];
    float* out = (float*)d_out;

    k_init<<<(NVOX / 4 + 255) / 256, 256>>>();
    k_segmax<<<256, 256>>>(ev);
    k_table<<<dim3((TABN + 127) / 128, 100 / KCH), 128>>>(W1, b1, W2, b2, W3, b3);
    k_scatter<<<(NEV + 255) / 256, 256>>>(ev);
    k_resize<<<(BB * 2 * CB * OUTSZ * (OUTSZ / 8) + 255) / 256, 256>>>(out);
}

// round 2
// speedup vs baseline: 1.0548x; 1.0548x over previous
#include <cuda_runtime.h>

// Problem constants (static per reference)
#define NEV   250000
#define CB    9
#define HV    180
#define WV    240
#define BB    8
#define PLANE (HV*WV)              // 43200
#define NVOX  (2*CB*PLANE*BB)      // 6,220,800
#define TABN  1025                 // table entries over s in [-1,1], h = 2/1024
#define TSHIFT 128.0f              // cells per bin shift: (1/8)/(2/1024) = 64 -> wait, see below
#define OUTSZ 640

// bin shift in table cells: (1/8) / (2/1024) = 64
#define BINCELLS 64.0f
#define TSCALE   512.0f            // (tn+1) * (1024/2)

__device__ float        g_vox[NVOX];
__device__ float        g_tab[TABN];
__device__ unsigned int g_bmax[BB];

// ---------------------------------------------------------------------------
// 0) zero vox / table / bmax
// ---------------------------------------------------------------------------
__global__ void k_init() {
    int i = blockIdx.x * blockDim.x + threadIdx.x;
    if (i < NVOX / 4) ((float4*)g_vox)[i] = make_float4(0.f, 0.f, 0.f, 0.f);
    if (i < TABN) g_tab[i] = 0.f;
    if (i < BB)   g_bmax[i] = 0u;
}

// ---------------------------------------------------------------------------
// 1) per-batch max of t (positive floats: uint order == float order)
// ---------------------------------------------------------------------------
__global__ void k_segmax(const float* __restrict__ ev) {
    __shared__ unsigned int sm[BB];
    if (threadIdx.x < BB) sm[threadIdx.x] = 0u;
    __syncthreads();
    for (int e = blockIdx.x * blockDim.x + threadIdx.x; e < NEV;
         e += gridDim.x * blockDim.x) {
        float t = __ldg(&ev[5 * e + 2]);
        int   b = (int)__ldg(&ev[5 * e + 4]);
        atomicMax(&sm[b], __float_as_uint(t));
    }
    __syncthreads();
    if (threadIdx.x < BB) atomicMax(&g_bmax[threadIdx.x], sm[threadIdx.x]);
}

// ---------------------------------------------------------------------------
// 2) tabulate f(s) on 1025-point grid; k-neurons split over gridDim.y.
// ---------------------------------------------------------------------------
#define KCH 25
__global__ void k_table(const float* __restrict__ W1, const float* __restrict__ b1,
                        const float* __restrict__ W2, const float* __restrict__ b2,
                        const float* __restrict__ W3, const float* __restrict__ b3) {
    __shared__ float sW2[100 * KCH];
    __shared__ float sW1[100], sb1[100];
    int k0 = blockIdx.y * KCH;
    for (int i = threadIdx.x; i < 100 * KCH; i += blockDim.x)
        sW2[i] = W2[(i / KCH) * 100 + k0 + (i % KCH)];
    for (int i = threadIdx.x; i < 100; i += blockDim.x) {
        sW1[i] = W1[i];
        sb1[i] = b1[i];
    }
    __syncthreads();
    int e = blockIdx.x * blockDim.x + threadIdx.x;
    if (e >= TABN) return;
    float s = (float)e * (2.0f / 1024.0f) - 1.0f;
    float acc[KCH];
#pragma unroll
    for (int k = 0; k < KCH; k++) acc[k] = 0.f;
#pragma unroll 4
    for (int j = 0; j < 100; j++) {
        float pre = fmaf(sW1[j], s, sb1[j]);
        float hj  = fmaxf(pre, 0.1f * pre);   // LeakyReLU(0.1)
#pragma unroll
        for (int k = 0; k < KCH; k++)
            acc[k] = fmaf(hj, sW2[j * KCH + k], acc[k]);
    }
    float f = (blockIdx.y == 0) ? b3[0] : 0.f;
#pragma unroll
    for (int k = 0; k < KCH; k++) {
        float pre = acc[k] + b2[k0 + k];
        float h2  = fmaxf(pre, 0.1f * pre);
        f = fmaf(h2, W3[k0 + k], f);
    }
    atomicAdd(&g_tab[e], f);
}

// ---------------------------------------------------------------------------
// 3) scatter with smem-staged coalesced event loads.
//    Each block handles 256 events: copy 1280 floats coalesced into smem
//    (kills the 5x L1 wavefront amplification of per-thread stride-5 loads),
//    then each thread reads its event from smem (stride 5 -> bank-conflict-free).
// ---------------------------------------------------------------------------
#define SCEV 256
__global__ void __launch_bounds__(SCEV) k_scatter(const float* __restrict__ ev) {
    __shared__ float se[SCEV * 5];
    int base = blockIdx.x * SCEV;
    int n = NEV - base;
    if (n > SCEV) n = SCEV;
    const float* src = ev + (size_t)base * 5;
    for (int i = threadIdx.x; i < 5 * n; i += SCEV) se[i] = src[i];
    __syncthreads();
    int tid = threadIdx.x;
    if (tid >= n) return;
    float x  = se[5 * tid + 0], y = se[5 * tid + 1], t = se[5 * tid + 2];
    float p  = se[5 * tid + 3], bf = se[5 * tid + 4];
    int b = (int)bf;
    float tn = t / __uint_as_float(g_bmax[b]);      // matches jnp fp32 divide
    int vbase = (int)x + WV * (int)y + (CB * PLANE) * (int)p + (2 * CB * PLANE) * b;
    float u0 = (tn + 1.0f) * TSCALE;                // grid coord of s = tn - 0
#pragma unroll
    for (int i = 0; i < CB; i++) {
        float u = u0 - BINCELLS * (float)i;         // exact fp32 arithmetic
        int i0 = (int)u;
        if (i0 > TABN - 2) i0 = TABN - 2;           // tn == 1.0 edge
        float fr = u - (float)i0;
        float t0 = g_tab[i0], t1 = g_tab[i0 + 1];
        float val = tn * fmaf(fr, t1 - t0, t0);
        atomicAdd(&g_vox[vbase + i * PLANE], val);
    }
}

// ---------------------------------------------------------------------------
// 4) letterbox bilinear resize (180,240)->(480,640), pad rows with 114.
//    scale = 8/3 exact; per 8 output columns the weights are compile-time
//    constants. Streaming stores (__stcs): out (236MB) exceeds L2, keep
//    vox/events L2-resident across graph replays.
// ---------------------------------------------------------------------------
__global__ void k_resize(float* __restrict__ out) {
    int gid = blockIdx.x * blockDim.x + threadIdx.x;   // 8*18*640*80
    if (gid >= BB * 2 * CB * OUTSZ * (OUTSZ / 8)) return;
    int m  = gid % (OUTSZ / 8);
    int r  = gid / (OUTSZ / 8);
    int oy = r % OUTSZ;
    int bc = r / OUTSZ;                                // b*18 + c
    float4* o = (float4*)(out + (((size_t)bc * OUTSZ + oy) * OUTSZ + m * 8));
    if (oy < 80 || oy >= 560) {
        float4 v = make_float4(114.f, 114.f, 114.f, 114.f);
        __stcs(o, v);
        __stcs(o + 1, v);
        return;
    }
    int c = bc % (2 * CB), b = bc / (2 * CB);
    int pp = c / CB, bin = c % CB;
    const float* vb = g_vox + (size_t)PLANE * (bin + CB * (pp + 2 * b));

    int oyr = oy - 80;
    float fy  = 0.375f * (float)oyr - 0.3125f;
    float fyf = floorf(fy);
    int   y0  = (int)fyf;
    float wy  = fy - fyf;
    int y0c = y0 < 0 ? 0 : y0;
    int y1c = (y0 + 1 > HV - 1) ? (HV - 1) : (y0 + 1);
    const float* r0 = vb + y0c * WV;
    const float* r1 = vb + y1c * WV;

    int xb = 3 * m - 1;
    float a0[5], a1[5];
#pragma unroll
    for (int i = 0; i < 5; i++) {
        int xc = xb + i;
        xc = xc < 0 ? 0 : (xc > WV - 1 ? WV - 1 : xc);
        a0[i] = __ldg(&r0[xc]);
        a1[i] = __ldg(&r1[xc]);
    }
    const float wx[8] = {0.6875f, 0.0625f, 0.4375f, 0.8125f,
                         0.1875f, 0.5625f, 0.9375f, 0.3125f};
    const int   ix[8] = {0, 1, 1, 1, 2, 2, 2, 3};
    float o8[8];
#pragma unroll
    for (int k = 0; k < 8; k++) {
        int i = ix[k];
        float h0 = fmaf(wx[k], a0[i + 1] - a0[i], a0[i]);
        float h1 = fmaf(wx[k], a1[i + 1] - a1[i], a1[i]);
        o8[k] = fmaf(wy, h1 - h0, h0);
    }
    __stcs(o,     make_float4(o8[0], o8[1], o8[2], o8[3]));
    __stcs(o + 1, make_float4(o8[4], o8[5], o8[6], o8[7]));
}

// ---------------------------------------------------------------------------
// launch: inputs per metadata order:
// events, W1, b1, W2, b2, W3, b3, batch_size(unused; B=8 static)
// ---------------------------------------------------------------------------
extern "C" void kernel_launch(void* const* d_in, const int* in_sizes, int n_in,
                              void* d_out, int out_size) {
    const float* ev = (const float*)d_in[0];
    const float* W1 = (const float*)d_in[1];
    const float* b1 = (const float*)d_in[2];
    const float* W2 = (const float*)d_in[3];
    const float* b2 = (const float*)d_in[4];
    const float* W3 = (const float*)d_in[5];
    const float* b3 = (const float*)d_in[6];
    float* out = (float*)d_out;

    k_init<<<(NVOX / 4 + 255) / 256, 256>>>();
    k_segmax<<<256, 256>>>(ev);
    k_table<<<dim3((TABN + 127) / 128, 100 / KCH), 128>>>(W1, b1, W2, b2, W3, b3);
    k_scatter<<<(NEV + SCEV - 1) / SCEV, SCEV>>>(ev);
    k_resize<<<(BB * 2 * CB * OUTSZ * (OUTSZ / 8) + 255) / 256, 256>>>(out);
}